// round 7
// baseline (speedup 1.0000x reference)
#include <cuda_runtime.h>
#include <math.h>
#include <stdint.h>

// ---------------- problem constants ----------------
#define BG    64
#define NA    32
#define HID   600
#define NG    50
#define NL    6
#define NTOT  (BG*NA)      // 2048
#define NE    (BG*NA*NA)   // 65536
#define PGRID 2047         // t = d * PGRID/10 in [0,2047]
#define PTAB  2049         // rows 0..2048 ; row r <-> d = r*10/2047
#define MSLICE 120         // message f-slice (5 slices of 120)

// ---------------- scratch layout (floats), 64-float aligned regions ----------------
#define AL64(x) (((x) + 63) & ~63)
#define O_H     0
#define O_XJ    AL64(O_H    + NTOT*HID)
#define O_M     AL64(O_XJ   + NTOT*HID)
#define O_T1    AL64(O_M    + NTOT*HID)
#define O_TAB   AL64(O_T1   + NTOT*HID)
#define O_TABA  AL64(O_TAB  + PTAB*HID)
#define O_RBFT  AL64(O_TABA + PTAB*HID)
#define O_COSW  AL64(O_RBFT + PTAB*NG)
#define O_TPOS  AL64(O_COSW + NE)
#define O_POOL  AL64(O_TPOS + NE)
#define SCRATCH_TOT AL64(O_POOL + BG*HID)

__device__ __align__(16) float g_scratch[SCRATCH_TOT];   // ~30 MB static scratch

// ---------------- helpers ----------------
__device__ __forceinline__ float sspf(float x) {
    return fmaxf(x, 0.f) + log1pf(expf(-fabsf(x))) - 0.69314718055994531f;
}
__device__ __forceinline__ uint32_t f2tf(float x) {
    uint32_t r;
    asm("cvt.rna.tf32.f32 %0, %1;" : "=r"(r) : "f"(x));
    return r;
}

#define FL_BIAS 1
#define FL_SSP  2
#define FL_RES  4

// ---------------- geometry: per-edge cosine cutoff + table position ----------------
__global__ void geom_k(const float* __restrict__ pos,
                       float* __restrict__ cosw, float* __restrict__ tpos) {
    int e = blockIdx.x * blockDim.x + threadIdx.x;
    if (e >= NE) return;
    int b = e >> 10;
    int r = e & 1023;
    int i = r >> 5, j = r & 31;
    int ai = b * NA + i, aj = b * NA + j;
    float dx = pos[ai*3+0] - pos[aj*3+0];
    float dy = pos[ai*3+1] - pos[aj*3+1];
    float dz = pos[ai*3+2] - pos[aj*3+2];
    float sq = dx*dx + dy*dy + dz*dz;
    float cw = 0.f, t = 0.f;
    if (i != j && sq <= 100.f) {
        float d = sqrtf(sq > 0.f ? sq : 1.f);
        cw = 0.5f * (cospif(d * 0.1f) + 1.f);
        t  = d * ((float)PGRID / 10.f);
    }
    cosw[e] = cw;
    tpos[e] = t;
}

// ---------------- RBF values at table nodes ----------------
__global__ void rbftab_k(float* __restrict__ rbfT) {
    int idx = blockIdx.x * blockDim.x + threadIdx.x;
    if (idx >= PTAB * NG) return;
    int p = idx / NG, g = idx % NG;
    float d   = (float)p * (10.f / (float)PGRID);   // row r <-> d = r*h
    float off = (float)g * (10.f / 49.f);           // linspace(0,10,50)
    float df  = d - off;
    const float coeff = -12.005f;                   // -0.5/(10/49)^2
    rbfT[idx] = expf(coeff * df * df);
}

// ---------------- atom embedding gather ----------------
__global__ void embed_k(const int* __restrict__ z, const float* __restrict__ emb,
                        float* __restrict__ h) {
    int idx = blockIdx.x * blockDim.x + threadIdx.x;
    if (idx >= NTOT * HID) return;
    int n = idx / HID, f = idx % HID;
    h[idx] = emb[z[n] * HID + f];
}

// ---------------- tf32 tensor-core GEMM, software-pipelined, 8 warps ----------------
// C = op(A[M,K] @ W[K,N] (+bias)) ; BM=BN=64, BK=32, 256 threads (8 warps 2x4),
// warp tile 32x16 via m16n8k8 tf32 mma. Register double-buffer hides LDG.
__global__ __launch_bounds__(256) void gemm_tc(
        const float* __restrict__ A, const float* __restrict__ W,
        const float* __restrict__ bias, float* __restrict__ C,
        int M, int N, int K, int flags) {
    __shared__ uint32_t As[32][72];   // [k][m] tf32 bits, conflict-free frag loads
    __shared__ uint32_t Bs[32][72];   // [k][n]

    int tid  = threadIdx.x;
    int row0 = blockIdx.y * 64, col0 = blockIdx.x * 64;
    int warp = tid >> 5, lane = tid & 31;
    int wm = (warp >> 2) * 32;        // warp row (2 rows of 32)
    int wn = (warp & 3) * 16;         // warp col (4 cols of 16)
    int g = lane >> 2, tig = lane & 3;

    bool k16 = ((K & 3) == 0);        // A rows 16B-aligned -> float4 path legal

    float c[2][2][4];
#pragma unroll
    for (int mi = 0; mi < 2; mi++)
#pragma unroll
        for (int ni = 0; ni < 2; ni++)
#pragma unroll
            for (int q = 0; q < 4; q++) c[mi][ni][q] = 0.f;

    float a_st[2][4], b_st[2][4];     // staging registers

    auto ldA = [&](int k0) {
#pragma unroll
        for (int l = 0; l < 2; l++) {
            int idx = tid + l * 256;          // 0..511
            int r   = idx >> 3;               // row 0..63
            int c4  = idx & 7;                // k-quad 0..7
            int grow = row0 + r;
            int kg   = k0 + c4 * 4;
            float v0 = 0.f, v1 = 0.f, v2 = 0.f, v3 = 0.f;
            if (grow < M) {
                if (k16 && (kg + 3 < K)) {
                    float4 t = *(const float4*)(A + (size_t)grow * K + kg);
                    v0 = t.x; v1 = t.y; v2 = t.z; v3 = t.w;
                } else {
                    if (kg + 0 < K) v0 = A[(size_t)grow * K + kg + 0];
                    if (kg + 1 < K) v1 = A[(size_t)grow * K + kg + 1];
                    if (kg + 2 < K) v2 = A[(size_t)grow * K + kg + 2];
                    if (kg + 3 < K) v3 = A[(size_t)grow * K + kg + 3];
                }
            }
            a_st[l][0] = v0; a_st[l][1] = v1; a_st[l][2] = v2; a_st[l][3] = v3;
        }
    };
    auto ldB = [&](int k0) {
#pragma unroll
        for (int l = 0; l < 2; l++) {
            int idx = tid + l * 256;
            int kk  = idx >> 4;               // k 0..31
            int c16 = idx & 15;               // n-quad 0..15
            int kg  = k0 + kk;
            int gc  = col0 + c16 * 4;
            float v0 = 0.f, v1 = 0.f, v2 = 0.f, v3 = 0.f;
            if (kg < K) {
                if (((N & 3) == 0) && (gc + 3 < N)) {
                    float4 t = *(const float4*)(W + (size_t)kg * N + gc);
                    v0 = t.x; v1 = t.y; v2 = t.z; v3 = t.w;
                } else {
                    if (gc + 0 < N) v0 = W[(size_t)kg * N + gc + 0];
                    if (gc + 1 < N) v1 = W[(size_t)kg * N + gc + 1];
                    if (gc + 2 < N) v2 = W[(size_t)kg * N + gc + 2];
                    if (gc + 3 < N) v3 = W[(size_t)kg * N + gc + 3];
                }
            }
            b_st[l][0] = v0; b_st[l][1] = v1; b_st[l][2] = v2; b_st[l][3] = v3;
        }
    };
    auto sts = [&]() {
#pragma unroll
        for (int l = 0; l < 2; l++) {
            int idx = tid + l * 256;
            int r   = idx >> 3;
            int c4  = idx & 7;
#pragma unroll
            for (int q = 0; q < 4; q++) As[c4 * 4 + q][r] = f2tf(a_st[l][q]);
            int kk  = idx >> 4;
            int c16 = idx & 15;
#pragma unroll
            for (int q = 0; q < 4; q++) Bs[kk][c16 * 4 + q] = f2tf(b_st[l][q]);
        }
    };

    int nk = (K + 31) >> 5;

    ldA(0); ldB(0);
    sts();
    __syncthreads();

    for (int kb = 0; kb < nk; kb++) {
        bool more = (kb + 1 < nk);
        if (more) { ldA((kb + 1) << 5); ldB((kb + 1) << 5); }  // LDGs in flight

#pragma unroll
        for (int ks = 0; ks < 4; ks++) {
            int kb8 = ks * 8;
            uint32_t a[2][4], b[2][2];
#pragma unroll
            for (int mi = 0; mi < 2; mi++) {
                int m = wm + mi * 16;
                a[mi][0] = As[kb8 + tig    ][m + g    ];
                a[mi][1] = As[kb8 + tig    ][m + g + 8];
                a[mi][2] = As[kb8 + tig + 4][m + g    ];
                a[mi][3] = As[kb8 + tig + 4][m + g + 8];
            }
#pragma unroll
            for (int ni = 0; ni < 2; ni++) {
                int n = wn + ni * 8;
                b[ni][0] = Bs[kb8 + tig    ][n + g];
                b[ni][1] = Bs[kb8 + tig + 4][n + g];
            }
#pragma unroll
            for (int mi = 0; mi < 2; mi++)
#pragma unroll
                for (int ni = 0; ni < 2; ni++) {
                    asm volatile(
                        "mma.sync.aligned.m16n8k8.row.col.f32.tf32.tf32.f32 "
                        "{%0,%1,%2,%3}, {%4,%5,%6,%7}, {%8,%9}, {%0,%1,%2,%3};\n"
                        : "+f"(c[mi][ni][0]), "+f"(c[mi][ni][1]),
                          "+f"(c[mi][ni][2]), "+f"(c[mi][ni][3])
                        : "r"(a[mi][0]), "r"(a[mi][1]), "r"(a[mi][2]), "r"(a[mi][3]),
                          "r"(b[ni][0]), "r"(b[ni][1]));
                }
        }
        if (more) {
            __syncthreads();
            sts();
            __syncthreads();
        }
    }

    // ---- epilogue ----
#pragma unroll
    for (int mi = 0; mi < 2; mi++) {
#pragma unroll
        for (int h01 = 0; h01 < 2; h01++) {
            int row = row0 + wm + mi * 16 + g + h01 * 8;
            if (row >= M) continue;
#pragma unroll
            for (int ni = 0; ni < 2; ni++) {
#pragma unroll
                for (int q = 0; q < 2; q++) {
                    int col = col0 + wn + ni * 8 + tig * 2 + q;
                    if (col >= N) continue;
                    float v = c[mi][ni][h01 * 2 + q];
                    if (flags & FL_BIAS) v += bias[col];
                    if (flags & FL_SSP)  v = sspf(v);
                    size_t idx = (size_t)row * N + col;
                    if (flags & FL_RES)  v += C[idx];
                    C[idx] = v;
                }
            }
        }
    }
}

// ---------------- symmetric message kernel ----------------
// block = (graph b, f-slice sl of 120). Lower-triangle pairs: wv computed once,
// applied to both directions. xj slice, m accumulators, pair metadata in smem.
__global__ __launch_bounds__(128) void message_sym_k(
        const float* __restrict__ cosw, const float* __restrict__ tpos,
        const float* __restrict__ tab,  const float* __restrict__ xj,
        float* __restrict__ m) {
    int b   = blockIdx.x;
    int f0  = blockIdx.y * MSLICE;
    int tid = threadIdx.x;

    __shared__ float xs[NA * MSLICE];
    __shared__ float ms[NA * MSLICE];
    __shared__ float cw_s[NA * NA];
    __shared__ float tp_s[NA * NA];

    for (int t = tid; t < NA * NA; t += 128) {
        cw_s[t] = cosw[b * NA * NA + t];
        tp_s[t] = tpos[b * NA * NA + t];
    }
    if (tid < MSLICE) {
        for (int j = 0; j < NA; j++) {
            xs[j * MSLICE + tid] = xj[(size_t)(b * NA + j) * HID + f0 + tid];
            ms[j * MSLICE + tid] = 0.f;
        }
    }
    __syncthreads();

    if (tid < MSLICE) {
        for (int i = 1; i < NA; i++) {
            float acc = 0.f;                         // accumulates into m[i]
            float xi  = xs[i * MSLICE + tid];
#pragma unroll 4
            for (int j = 0; j < i; j++) {
                float cw = cw_s[i * NA + j];
                float t  = tp_s[i * NA + j];
                int u = (int)t;
                if (u > PGRID) u = PGRID;
                float s  = t - (float)u;
                float w1 = s * cw;
                float w0 = cw - w1;
                float t0 = tab[(size_t)u * HID + f0 + tid];
                float t1 = tab[(size_t)(u + 1) * HID + f0 + tid];
                float wv = fmaf(w0, t0, w1 * t1);    // zero for masked pairs
                acc = fmaf(wv, xs[j * MSLICE + tid], acc);
                ms[j * MSLICE + tid] = fmaf(wv, xi, ms[j * MSLICE + tid]);
            }
            ms[i * MSLICE + tid] += acc;
        }
        for (int i = 0; i < NA; i++)
            m[(size_t)(b * NA + i) * HID + f0 + tid] = ms[i * MSLICE + tid];
    }
}

// ---------------- per-graph mean pool ----------------
__global__ void pool_k(const float* __restrict__ h, float* __restrict__ pool) {
    int idx = blockIdx.x * blockDim.x + threadIdx.x;
    if (idx >= BG * HID) return;
    int b = idx / HID, f = idx % HID;
    float s = 0.f;
#pragma unroll
    for (int i = 0; i < NA; i++) s += h[(size_t)(b * NA + i) * HID + f];
    pool[idx] = s * (1.f / (float)NA);
}

// ---------------- host launch ----------------
extern "C" void kernel_launch(void* const* d_in, const int* in_sizes, int n_in,
                              void* d_out, int out_size) {
    const int*   z    = (const int*)  d_in[0];
    const float* pos  = (const float*)d_in[1];
    const float* emb  = (const float*)d_in[3];
    const float* w1   = (const float*)d_in[4];
    const float* b1   = (const float*)d_in[5];
    const float* w2   = (const float*)d_in[6];
    const float* b2   = (const float*)d_in[7];
    const float* l1w  = (const float*)d_in[8];
    const float* l2w  = (const float*)d_in[9];
    const float* l2b  = (const float*)d_in[10];
    const float* lw   = (const float*)d_in[11];
    const float* lb   = (const float*)d_in[12];
    const float* pw   = (const float*)d_in[13];
    const float* pb   = (const float*)d_in[14];
    float* out = (float*)d_out;

    float* S = nullptr;
    cudaGetSymbolAddress((void**)&S, g_scratch);
    float* H  = S + O_H;
    float* XJ = S + O_XJ;
    float* MM = S + O_M;
    float* T1 = S + O_T1;
    float* TB = S + O_TAB;
    float* TA = S + O_TABA;
    float* RB = S + O_RBFT;
    float* CW = S + O_COSW;
    float* TP = S + O_TPOS;
    float* PL = S + O_POOL;

    geom_k  <<<(NE + 255) / 256, 256>>>(pos, CW, TP);
    rbftab_k<<<(PTAB * NG + 255) / 256, 256>>>(RB);
    embed_k <<<(NTOT * HID + 255) / 256, 256>>>(z, emb, H);

    dim3 gN((HID + 63) / 64, (NTOT + 63) / 64);   // (10, 32)
    dim3 gT((HID + 63) / 64, (PTAB + 63) / 64);   // (10, 33)
    dim3 gM(BG, HID / MSLICE);                    // (64, 5)

    for (int L = 0; L < NL; L++) {
        const float* w1L  = w1  + (size_t)L * NG  * HID;
        const float* b1L  = b1  + (size_t)L * HID;
        const float* w2L  = w2  + (size_t)L * HID * HID;
        const float* b2L  = b2  + (size_t)L * HID;
        const float* l1wL = l1w + (size_t)L * HID * HID;
        const float* l2wL = l2w + (size_t)L * HID * HID;
        const float* l2bL = l2b + (size_t)L * HID;
        const float* lwL  = lw  + (size_t)L * HID * HID;
        const float* lbL  = lb  + (size_t)L * HID;

        // filter-table build: TA = ssp(RB @ w1 + b1) ; TB = TA @ w2 + b2
        gemm_tc<<<gT, 256>>>(RB, w1L, b1L, TA, PTAB, HID, NG,  FL_BIAS | FL_SSP);
        gemm_tc<<<gT, 256>>>(TA, w2L, b2L, TB, PTAB, HID, HID, FL_BIAS);
        // xj = h @ lin1 (no bias)
        gemm_tc<<<gN, 256>>>(H, l1wL, nullptr, XJ, NTOT, HID, HID, 0);
        // symmetric fused interpolate + scatter-reduce message
        message_sym_k<<<gM, 128>>>(CW, TP, TB, XJ, MM);
        // v = ssp(m @ l2w + l2b) @ lw + lb ; h += v
        gemm_tc<<<gN, 256>>>(MM, l2wL, l2bL, T1, NTOT, HID, HID, FL_BIAS | FL_SSP);
        gemm_tc<<<gN, 256>>>(T1, lwL,  lbL,  H,  NTOT, HID, HID, FL_BIAS | FL_RES);
    }

    pool_k<<<(BG * HID + 255) / 256, 256>>>(H, PL);
    gemm_tc<<<dim3((HID + 63) / 64, 1), 256>>>(PL, pw, pb, out, BG, HID, HID, FL_BIAS);
}

// round 8
// speedup vs baseline: 1.3899x; 1.3899x over previous
#include <cuda_runtime.h>
#include <math.h>
#include <stdint.h>

// ---------------- problem constants ----------------
#define BG    64
#define NA    32
#define HID   600
#define NG    50
#define NL    6
#define NTOT  (BG*NA)      // 2048
#define NE    (BG*NA*NA)   // 65536
#define PGRID 2047         // t = d * PGRID/10 in [0,2047]
#define PTAB  2049         // rows 0..2048 ; row r <-> d = r*10/2047

// ---------------- scratch layout (floats), 64-float aligned regions ----------------
#define AL64(x) (((x) + 63) & ~63)
#define O_H     0
#define O_XJ    AL64(O_H    + NTOT*HID)
#define O_M     AL64(O_XJ   + NTOT*HID)
#define O_T1    AL64(O_M    + NTOT*HID)
#define O_TAB   AL64(O_T1   + NTOT*HID)
#define O_TABA  AL64(O_TAB  + PTAB*HID)
#define O_RBFT  AL64(O_TABA + PTAB*HID)
#define O_EU    AL64(O_RBFT + PTAB*NG)    // per-edge table index (int bits)
#define O_EW0   AL64(O_EU   + NE)         // per-edge weight 0 (cw folded)
#define O_EW1   AL64(O_EW0  + NE)         // per-edge weight 1
#define O_POOL  AL64(O_EW1  + NE)
#define SCRATCH_TOT AL64(O_POOL + BG*HID)

__device__ __align__(16) float g_scratch[SCRATCH_TOT];   // ~30 MB static scratch

// ---------------- helpers ----------------
__device__ __forceinline__ float sspf(float x) {
    return fmaxf(x, 0.f) + log1pf(expf(-fabsf(x))) - 0.69314718055994531f;
}
__device__ __forceinline__ uint32_t f2tf(float x) {
    uint32_t r;
    asm("cvt.rna.tf32.f32 %0, %1;" : "=r"(r) : "f"(x));
    return r;
}

#define FL_BIAS 1
#define FL_SSP  2
#define FL_RES  4

// ---------------- geometry: per-edge interp index + folded lerp weights ----------------
__global__ void geom_k(const float* __restrict__ pos,
                       int* __restrict__ eu, float* __restrict__ ew0,
                       float* __restrict__ ew1) {
    int e = blockIdx.x * blockDim.x + threadIdx.x;
    if (e >= NE) return;
    int b = e >> 10;
    int r = e & 1023;
    int i = r >> 5, j = r & 31;
    int ai = b * NA + i, aj = b * NA + j;
    float dx = pos[ai*3+0] - pos[aj*3+0];
    float dy = pos[ai*3+1] - pos[aj*3+1];
    float dz = pos[ai*3+2] - pos[aj*3+2];
    float sq = dx*dx + dy*dy + dz*dz;
    int   u  = 0;
    float w0 = 0.f, w1 = 0.f;
    if (i != j && sq <= 100.f) {
        float d  = sqrtf(sq > 0.f ? sq : 1.f);
        float cw = 0.5f * (cospif(d * 0.1f) + 1.f);
        float t  = d * ((float)PGRID / 10.f);
        u = (int)t;
        if (u > PGRID) u = PGRID;
        float s = t - (float)u;
        w1 = s * cw;
        w0 = cw - w1;
    }
    eu[e]  = u;
    ew0[e] = w0;
    ew1[e] = w1;
}

// ---------------- RBF values at table nodes ----------------
__global__ void rbftab_k(float* __restrict__ rbfT) {
    int idx = blockIdx.x * blockDim.x + threadIdx.x;
    if (idx >= PTAB * NG) return;
    int p = idx / NG, g = idx % NG;
    float d   = (float)p * (10.f / (float)PGRID);   // row r <-> d = r*h
    float off = (float)g * (10.f / 49.f);           // linspace(0,10,50)
    float df  = d - off;
    const float coeff = -12.005f;                   // -0.5/(10/49)^2
    rbfT[idx] = expf(coeff * df * df);
}

// ---------------- atom embedding gather ----------------
__global__ void embed_k(const int* __restrict__ z, const float* __restrict__ emb,
                        float* __restrict__ h) {
    int idx = blockIdx.x * blockDim.x + threadIdx.x;
    if (idx >= NTOT * HID) return;
    int n = idx / HID, f = idx % HID;
    h[idx] = emb[z[n] * HID + f];
}

// ---------------- tf32 tensor-core GEMM, software-pipelined, 8 warps ----------------
// C = op(A[M,K] @ W[K,N] (+bias)) ; BM=BN=64, BK=32, 256 threads (8 warps 2x4),
// warp tile 32x16 via m16n8k8 tf32 mma. Register double-buffer hides LDG.
__global__ __launch_bounds__(256) void gemm_tc(
        const float* __restrict__ A, const float* __restrict__ W,
        const float* __restrict__ bias, float* __restrict__ C,
        int M, int N, int K, int flags) {
    __shared__ uint32_t As[32][72];   // [k][m] tf32 bits, conflict-free frag loads
    __shared__ uint32_t Bs[32][72];   // [k][n]

    int tid  = threadIdx.x;
    int row0 = blockIdx.y * 64, col0 = blockIdx.x * 64;
    int warp = tid >> 5, lane = tid & 31;
    int wm = (warp >> 2) * 32;        // warp row (2 rows of 32)
    int wn = (warp & 3) * 16;         // warp col (4 cols of 16)
    int g = lane >> 2, tig = lane & 3;

    bool k16 = ((K & 3) == 0);        // A rows 16B-aligned -> float4 path legal

    float c[2][2][4];
#pragma unroll
    for (int mi = 0; mi < 2; mi++)
#pragma unroll
        for (int ni = 0; ni < 2; ni++)
#pragma unroll
            for (int q = 0; q < 4; q++) c[mi][ni][q] = 0.f;

    float a_st[2][4], b_st[2][4];     // staging registers

    auto ldA = [&](int k0) {
#pragma unroll
        for (int l = 0; l < 2; l++) {
            int idx = tid + l * 256;          // 0..511
            int r   = idx >> 3;               // row 0..63
            int c4  = idx & 7;                // k-quad 0..7
            int grow = row0 + r;
            int kg   = k0 + c4 * 4;
            float v0 = 0.f, v1 = 0.f, v2 = 0.f, v3 = 0.f;
            if (grow < M) {
                if (k16 && (kg + 3 < K)) {
                    float4 t = *(const float4*)(A + (size_t)grow * K + kg);
                    v0 = t.x; v1 = t.y; v2 = t.z; v3 = t.w;
                } else {
                    if (kg + 0 < K) v0 = A[(size_t)grow * K + kg + 0];
                    if (kg + 1 < K) v1 = A[(size_t)grow * K + kg + 1];
                    if (kg + 2 < K) v2 = A[(size_t)grow * K + kg + 2];
                    if (kg + 3 < K) v3 = A[(size_t)grow * K + kg + 3];
                }
            }
            a_st[l][0] = v0; a_st[l][1] = v1; a_st[l][2] = v2; a_st[l][3] = v3;
        }
    };
    auto ldB = [&](int k0) {
#pragma unroll
        for (int l = 0; l < 2; l++) {
            int idx = tid + l * 256;
            int kk  = idx >> 4;               // k 0..31
            int c16 = idx & 15;               // n-quad 0..15
            int kg  = k0 + kk;
            int gc  = col0 + c16 * 4;
            float v0 = 0.f, v1 = 0.f, v2 = 0.f, v3 = 0.f;
            if (kg < K) {
                if (((N & 3) == 0) && (gc + 3 < N)) {
                    float4 t = *(const float4*)(W + (size_t)kg * N + gc);
                    v0 = t.x; v1 = t.y; v2 = t.z; v3 = t.w;
                } else {
                    if (gc + 0 < N) v0 = W[(size_t)kg * N + gc + 0];
                    if (gc + 1 < N) v1 = W[(size_t)kg * N + gc + 1];
                    if (gc + 2 < N) v2 = W[(size_t)kg * N + gc + 2];
                    if (gc + 3 < N) v3 = W[(size_t)kg * N + gc + 3];
                }
            }
            b_st[l][0] = v0; b_st[l][1] = v1; b_st[l][2] = v2; b_st[l][3] = v3;
        }
    };
    auto sts = [&]() {
#pragma unroll
        for (int l = 0; l < 2; l++) {
            int idx = tid + l * 256;
            int r   = idx >> 3;
            int c4  = idx & 7;
#pragma unroll
            for (int q = 0; q < 4; q++) As[c4 * 4 + q][r] = f2tf(a_st[l][q]);
            int kk  = idx >> 4;
            int c16 = idx & 15;
#pragma unroll
            for (int q = 0; q < 4; q++) Bs[kk][c16 * 4 + q] = f2tf(b_st[l][q]);
        }
    };

    int nk = (K + 31) >> 5;

    ldA(0); ldB(0);
    sts();
    __syncthreads();

    for (int kb = 0; kb < nk; kb++) {
        bool more = (kb + 1 < nk);
        if (more) { ldA((kb + 1) << 5); ldB((kb + 1) << 5); }  // LDGs in flight

#pragma unroll
        for (int ks = 0; ks < 4; ks++) {
            int kb8 = ks * 8;
            uint32_t a[2][4], b[2][2];
#pragma unroll
            for (int mi = 0; mi < 2; mi++) {
                int m = wm + mi * 16;
                a[mi][0] = As[kb8 + tig    ][m + g    ];
                a[mi][1] = As[kb8 + tig    ][m + g + 8];
                a[mi][2] = As[kb8 + tig + 4][m + g    ];
                a[mi][3] = As[kb8 + tig + 4][m + g + 8];
            }
#pragma unroll
            for (int ni = 0; ni < 2; ni++) {
                int n = wn + ni * 8;
                b[ni][0] = Bs[kb8 + tig    ][n + g];
                b[ni][1] = Bs[kb8 + tig + 4][n + g];
            }
#pragma unroll
            for (int mi = 0; mi < 2; mi++)
#pragma unroll
                for (int ni = 0; ni < 2; ni++) {
                    asm volatile(
                        "mma.sync.aligned.m16n8k8.row.col.f32.tf32.tf32.f32 "
                        "{%0,%1,%2,%3}, {%4,%5,%6,%7}, {%8,%9}, {%0,%1,%2,%3};\n"
                        : "+f"(c[mi][ni][0]), "+f"(c[mi][ni][1]),
                          "+f"(c[mi][ni][2]), "+f"(c[mi][ni][3])
                        : "r"(a[mi][0]), "r"(a[mi][1]), "r"(a[mi][2]), "r"(a[mi][3]),
                          "r"(b[ni][0]), "r"(b[ni][1]));
                }
        }
        if (more) {
            __syncthreads();
            sts();
            __syncthreads();
        }
    }

    // ---- epilogue ----
#pragma unroll
    for (int mi = 0; mi < 2; mi++) {
#pragma unroll
        for (int h01 = 0; h01 < 2; h01++) {
            int row = row0 + wm + mi * 16 + g + h01 * 8;
            if (row >= M) continue;
#pragma unroll
            for (int ni = 0; ni < 2; ni++) {
#pragma unroll
                for (int q = 0; q < 2; q++) {
                    int col = col0 + wn + ni * 8 + tig * 2 + q;
                    if (col >= N) continue;
                    float v = c[mi][ni][h01 * 2 + q];
                    if (flags & FL_BIAS) v += bias[col];
                    if (flags & FL_SSP)  v = sspf(v);
                    size_t idx = (size_t)row * N + col;
                    if (flags & FL_RES)  v += C[idx];
                    C[idx] = v;
                }
            }
        }
    }
}

// ---------------- message: m[b,i,f] = sum_j lerp(tab,u,w)[f] * xj[b,j,f] ----------------
// Branch-free: edge metadata preloaded to smem; unrolled j-loop keeps many
// independent LDG.128 in flight (masked edges have w0=w1=0, u=0 stays hot).
__global__ __launch_bounds__(128) void message_k(
        const int* __restrict__ eu, const float* __restrict__ ew0,
        const float* __restrict__ ew1,
        const float* __restrict__ tab,  const float* __restrict__ xj,
        float* __restrict__ m) {
    int bi = blockIdx.x;          // b*32 + i
    int b  = bi >> 5;
    int tid = threadIdx.x;        // 128 threads; chunks tid and tid+128 of 150 float4

    __shared__ int   us[NA];
    __shared__ float w0s[NA], w1s[NA];
    if (tid < NA) {
        int e = bi * NA + tid;
        us[tid]  = eu[e];
        w0s[tid] = ew0[e];
        w1s[tid] = ew1[e];
    }
    __syncthreads();

    float4 acc0 = make_float4(0.f, 0.f, 0.f, 0.f);
    float4 acc1 = make_float4(0.f, 0.f, 0.f, 0.f);
    const float* xb = xj + (size_t)(b * NA) * HID;

#pragma unroll 4
    for (int j = 0; j < NA; j++) {
        int   u  = us[j];
        float w0 = w0s[j], w1 = w1s[j];
        const float4* T0 = (const float4*)(tab + (size_t)u * HID);
        const float4* T1 = (const float4*)(tab + (size_t)(u + 1) * HID);
        const float4* xr = (const float4*)(xb + (size_t)j * HID);
        {
            float4 t0 = T0[tid], t1 = T1[tid], x = xr[tid];
            acc0.x = fmaf(fmaf(w0, t0.x, w1 * t1.x), x.x, acc0.x);
            acc0.y = fmaf(fmaf(w0, t0.y, w1 * t1.y), x.y, acc0.y);
            acc0.z = fmaf(fmaf(w0, t0.z, w1 * t1.z), x.z, acc0.z);
            acc0.w = fmaf(fmaf(w0, t0.w, w1 * t1.w), x.w, acc0.w);
        }
        if (tid < 22) {
            int q = tid + 128;
            float4 t0 = T0[q], t1 = T1[q], x = xr[q];
            acc1.x = fmaf(fmaf(w0, t0.x, w1 * t1.x), x.x, acc1.x);
            acc1.y = fmaf(fmaf(w0, t0.y, w1 * t1.y), x.y, acc1.y);
            acc1.z = fmaf(fmaf(w0, t0.z, w1 * t1.z), x.z, acc1.z);
            acc1.w = fmaf(fmaf(w0, t0.w, w1 * t1.w), x.w, acc1.w);
        }
    }
    float4* mr = (float4*)(m + (size_t)bi * HID);
    mr[tid] = acc0;
    if (tid < 22) mr[tid + 128] = acc1;
}

// ---------------- per-graph mean pool ----------------
__global__ void pool_k(const float* __restrict__ h, float* __restrict__ pool) {
    int idx = blockIdx.x * blockDim.x + threadIdx.x;
    if (idx >= BG * HID) return;
    int b = idx / HID, f = idx % HID;
    float s = 0.f;
#pragma unroll
    for (int i = 0; i < NA; i++) s += h[(size_t)(b * NA + i) * HID + f];
    pool[idx] = s * (1.f / (float)NA);
}

// ---------------- host launch ----------------
extern "C" void kernel_launch(void* const* d_in, const int* in_sizes, int n_in,
                              void* d_out, int out_size) {
    const int*   z    = (const int*)  d_in[0];
    const float* pos  = (const float*)d_in[1];
    const float* emb  = (const float*)d_in[3];
    const float* w1   = (const float*)d_in[4];
    const float* b1   = (const float*)d_in[5];
    const float* w2   = (const float*)d_in[6];
    const float* b2   = (const float*)d_in[7];
    const float* l1w  = (const float*)d_in[8];
    const float* l2w  = (const float*)d_in[9];
    const float* l2b  = (const float*)d_in[10];
    const float* lw   = (const float*)d_in[11];
    const float* lb   = (const float*)d_in[12];
    const float* pw   = (const float*)d_in[13];
    const float* pb   = (const float*)d_in[14];
    float* out = (float*)d_out;

    float* S = nullptr;
    cudaGetSymbolAddress((void**)&S, g_scratch);
    float* H  = S + O_H;
    float* XJ = S + O_XJ;
    float* MM = S + O_M;
    float* T1 = S + O_T1;
    float* TB = S + O_TAB;
    float* TA = S + O_TABA;
    float* RB = S + O_RBFT;
    int*   EU = (int*)(S + O_EU);
    float* E0 = S + O_EW0;
    float* E1 = S + O_EW1;
    float* PL = S + O_POOL;

    geom_k  <<<(NE + 255) / 256, 256>>>(pos, EU, E0, E1);
    rbftab_k<<<(PTAB * NG + 255) / 256, 256>>>(RB);
    embed_k <<<(NTOT * HID + 255) / 256, 256>>>(z, emb, H);

    dim3 gN((HID + 63) / 64, (NTOT + 63) / 64);   // (10, 32)
    dim3 gT((HID + 63) / 64, (PTAB + 63) / 64);   // (10, 33)

    for (int L = 0; L < NL; L++) {
        const float* w1L  = w1  + (size_t)L * NG  * HID;
        const float* b1L  = b1  + (size_t)L * HID;
        const float* w2L  = w2  + (size_t)L * HID * HID;
        const float* b2L  = b2  + (size_t)L * HID;
        const float* l1wL = l1w + (size_t)L * HID * HID;
        const float* l2wL = l2w + (size_t)L * HID * HID;
        const float* l2bL = l2b + (size_t)L * HID;
        const float* lwL  = lw  + (size_t)L * HID * HID;
        const float* lbL  = lb  + (size_t)L * HID;

        // filter-table build: TA = ssp(RB @ w1 + b1) ; TB = TA @ w2 + b2
        gemm_tc<<<gT, 256>>>(RB, w1L, b1L, TA, PTAB, HID, NG,  FL_BIAS | FL_SSP);
        gemm_tc<<<gT, 256>>>(TA, w2L, b2L, TB, PTAB, HID, HID, FL_BIAS);
        // xj = h @ lin1 (no bias)
        gemm_tc<<<gN, 256>>>(H, l1wL, nullptr, XJ, NTOT, HID, HID, 0);
        // fused interpolate + scatter-reduce message (branch-free, unrolled)
        message_k<<<NTOT, 128>>>(EU, E0, E1, TB, XJ, MM);
        // v = ssp(m @ l2w + l2b) @ lw + lb ; h += v
        gemm_tc<<<gN, 256>>>(MM, l2wL, l2bL, T1, NTOT, HID, HID, FL_BIAS | FL_SSP);
        gemm_tc<<<gN, 256>>>(T1, lwL,  lbL,  H,  NTOT, HID, HID, FL_BIAS | FL_RES);
    }

    pool_k<<<(BG * HID + 255) / 256, 256>>>(H, PL);
    gemm_tc<<<dim3((HID + 63) / 64, 1), 256>>>(PL, pw, pb, out, BG, HID, HID, FL_BIAS);
}